// round 1
// baseline (speedup 1.0000x reference)
#include <cuda_runtime.h>

#define BB 8192
#define FF 32
#define EE 64
#define PP 496   // 32 choose 2

__global__ __launch_bounds__(256, 1)
void bilinear_pair_kernel(const float* __restrict__ x,
                          const float* __restrict__ W,
                          float* __restrict__ out)
{
    __shared__ float Ws[EE][EE];   // 16 KB   W[e][d]
    __shared__ float xs[FF][EE];   // 8 KB    x[b][f][e]
    __shared__ float xws[FF][EE];  // 8 KB    (x[b] @ W)[f][d]

    const int b   = blockIdx.x;
    const int tid = threadIdx.x;

    // ---- load W (4096 floats) and x[b] (2048 floats) as float4 ----
    {
        const float4* W4  = (const float4*)W;
        float4*       Ws4 = (float4*)&Ws[0][0];
        #pragma unroll
        for (int k = tid; k < EE * EE / 4; k += 256)
            Ws4[k] = W4[k];

        const float4* x4  = (const float4*)(x + (size_t)b * FF * EE);
        float4*       xs4 = (float4*)&xs[0][0];
        #pragma unroll
        for (int k = tid; k < FF * EE / 4; k += 256)
            xs4[k] = x4[k];
    }
    __syncthreads();

    // ---- xw[f][d] = sum_e xs[f][e] * Ws[e][d] ; 2048 outputs, 8/thread ----
    #pragma unroll
    for (int r = 0; r < 8; r++) {
        int idx = tid + r * 256;
        int row = idx >> 6;
        int col = idx & 63;
        float acc = 0.f;
        #pragma unroll
        for (int e = 0; e < EE; e++)
            acc = fmaf(xs[row][e], Ws[e][col], acc);
        xws[row][col] = acc;
    }
    __syncthreads();

    // ---- stream 496 pairs x 64 floats, coalesced float4 stores ----
    float4* out4 = (float4*)(out + (size_t)b * PP * EE);
    const int lane16 = tid & 15;   // which float4 within the 64-wide row
    const int pbase  = tid >> 4;   // 16 pairs handled per iteration

    for (int p = pbase; p < PP; p += 16) {
        // invert p -> (i, j): C(i) = i*(63-i)/2 pairs before row i
        int i = (int)((63.0f - sqrtf(3969.0f - 8.0f * (float)p)) * 0.5f);
        while (i * (63 - i) / 2 > p)            i--;
        while ((i + 1) * (62 - i) / 2 <= p)     i++;
        int j = p - i * (63 - i) / 2 + i + 1;

        float4 a = ((const float4*)&xws[i][0])[lane16];
        float4 c = ((const float4*)&xs[j][0])[lane16];
        float4 r;
        r.x = a.x * c.x;
        r.y = a.y * c.y;
        r.z = a.z * c.z;
        r.w = a.w * c.w;
        // streaming store: output (1 GB) has zero reuse, evict-first
        __stcs(&out4[p * 16 + lane16], r);
    }
}

extern "C" void kernel_launch(void* const* d_in, const int* in_sizes, int n_in,
                              void* d_out, int out_size)
{
    const float* x = (const float*)d_in[0];
    const float* W = (const float*)d_in[1];
    float*       o = (float*)d_out;
    bilinear_pair_kernel<<<BB, 256>>>(x, W, o);
}